// round 10
// baseline (speedup 1.0000x reference)
#include <cuda_runtime.h>
#include <cuda_fp16.h>
#include <cstdint>

// ---------------------------------------------------------------------------
// 2-layer GCN:  out = gcn(relu(gcn(x, W1, b1)), W2, b2)
// gcn(x,W,b)[v] = dis[v] * ( hs[v] + sum_{e: src->v} hs[src] ) + b
//   hs = (x @ W) * dis[row],  dis[v] = rsqrt(1 + indeg(v))
// GEMMs: fp16 mma.sync m16n8k16, fp32 accumulate. hs/x2 buffers fp16.
// Aggregation: pull-based CSR gather, 4-way MLP unroll.
// CSR build: memset + 5 kernels (dis fused into scan, cursor into offsets).
// ---------------------------------------------------------------------------

#define NNODES 100000
#define NEDGES 1600000
#define INC 128
#define HIDC 128
#define OUTC 64

// -------------------- scratch (device globals; no runtime alloc) -----------
__device__ int    g_cnt[NNODES];
__device__ int    g_cursor[NNODES];
__device__ int    g_rowptr[NNODES + 1];
__device__ int    g_partial[1024];
__device__ int    g_csr[NEDGES];
__device__ float  g_dis[NNODES];
__device__ __half g_hs1[(size_t)NNODES * HIDC];  // (x@W1)*dis
__device__ __half g_x2 [(size_t)NNODES * HIDC];  // relu(layer1 out)
__device__ __half g_hs2[(size_t)NNODES * OUTC];  // (x2@W2)*dis

// -------------------- mma helper --------------------------------------------
__device__ __forceinline__ void mma_f16(float* c, const uint32_t* a,
                                        uint32_t b0, uint32_t b1) {
    asm volatile(
        "mma.sync.aligned.m16n8k16.row.col.f32.f16.f16.f32 "
        "{%0,%1,%2,%3}, {%4,%5,%6,%7}, {%8,%9}, {%0,%1,%2,%3};"
        : "+f"(c[0]), "+f"(c[1]), "+f"(c[2]), "+f"(c[3])
        : "r"(a[0]), "r"(a[1]), "r"(a[2]), "r"(a[3]), "r"(b0), "r"(b1));
}

// -------------------- CSR build ---------------------------------------------
__global__ void k_count(const int* __restrict__ dst, int e) {
    int i = blockIdx.x * blockDim.x + threadIdx.x;
    if (i < e) atomicAdd(&g_cnt[dst[i]], 1);
}

// block-local exclusive scan of counts + dis computation
__global__ void k_scan_blocks(int n) {
    __shared__ int warpsum[8];
    int idx  = blockIdx.x * 256 + threadIdx.x;
    int lane = threadIdx.x & 31;
    int w    = threadIdx.x >> 5;
    int x    = (idx < n) ? g_cnt[idx] : 0;
    if (idx < n) g_dis[idx] = rsqrtf((float)(x + 1));
    int incl = x;
    #pragma unroll
    for (int o = 1; o < 32; o <<= 1) {
        int t = __shfl_up_sync(0xffffffffu, incl, o);
        if (lane >= o) incl += t;
    }
    if (lane == 31) warpsum[w] = incl;
    __syncthreads();
    if (w == 0) {
        int s = (lane < 8) ? warpsum[lane] : 0;
        #pragma unroll
        for (int o = 1; o < 8; o <<= 1) {
            int t = __shfl_up_sync(0xffffffffu, s, o);
            if (lane >= o) s += t;
        }
        if (lane < 8) warpsum[lane] = s;
    }
    __syncthreads();
    if (w > 0) incl += warpsum[w - 1];
    if (idx < n) g_rowptr[idx] = incl - x;
    if (threadIdx.x == 255) g_partial[blockIdx.x] = incl;
}

__global__ void k_scan_partials(int nb, int n) {
    __shared__ int warpsum[16];
    int tid  = threadIdx.x;
    int lane = tid & 31;
    int w    = tid >> 5;
    int x    = (tid < nb) ? g_partial[tid] : 0;
    int incl = x;
    #pragma unroll
    for (int o = 1; o < 32; o <<= 1) {
        int t = __shfl_up_sync(0xffffffffu, incl, o);
        if (lane >= o) incl += t;
    }
    if (lane == 31) warpsum[w] = incl;
    __syncthreads();
    if (w == 0) {
        int s = (lane < 16) ? warpsum[lane] : 0;
        #pragma unroll
        for (int o = 1; o < 16; o <<= 1) {
            int t = __shfl_up_sync(0xffffffffu, s, o);
            if (lane >= o) s += t;
        }
        if (lane < 16) warpsum[lane] = s;
    }
    __syncthreads();
    if (w > 0) incl += warpsum[w - 1];
    if (tid < nb) g_partial[tid] = incl - x;
    if (tid == nb - 1) g_rowptr[n] = incl;
}

// add block offsets to rowptr; init fill cursor to absolute row start
__global__ void k_add_offsets(int n) {
    int idx = blockIdx.x * 256 + threadIdx.x;
    if (idx < n) {
        int v = g_rowptr[idx] + g_partial[blockIdx.x];
        g_rowptr[idx] = v;
        g_cursor[idx] = v;
    }
}

__global__ void k_fill(const int* __restrict__ src, const int* __restrict__ dst, int e) {
    int i = blockIdx.x * blockDim.x + threadIdx.x;
    if (i < e) {
        int p = atomicAdd(&g_cursor[dst[i]], 1);
        g_csr[p] = src[i];
    }
}

// -------------------- GEMM 1 (fp16 mma m16n8k16): hs1 = (X@W1)*dis ---------
// CTA 128m x 128n, K=128. As [row][k] half (stride 136), Bs [n][k] half.
// 8 warps of 32m x 64n. smem = 69.6 KB -> 3 CTAs/SM.
#define SH_STRIDE 136
#define G1_SMEM ((128 * SH_STRIDE + 128 * SH_STRIDE) * 2)

__global__ void __launch_bounds__(256)
k_gemm1_mma(const float* __restrict__ X, const float* __restrict__ W, int m) {
    extern __shared__ __half sh[];
    __half* As = sh;                       // [128][136]  row-major (k contig)
    __half* Bs = sh + 128 * SH_STRIDE;     // [128][136]  n-major  (k contig)
    const int tid  = threadIdx.x;
    const int lane = tid & 31;
    const int wid  = tid >> 5;
    const int gr   = lane >> 2;
    const int gc   = lane & 3;
    const int bm   = blockIdx.x * 128;
    const int m0   = (wid & 3) * 32;
    const int n0   = (wid >> 2) * 64;

    // A fill: X fp32 -> fp16
    #pragma unroll
    for (int i = 0; i < 16; i++) {
        int f = tid + i * 256;             // 0..4095 float4
        int r = f >> 5, c4 = (f & 31) * 4;
        float4 v = make_float4(0.f, 0.f, 0.f, 0.f);
        if (bm + r < m) v = *(const float4*)(X + (size_t)(bm + r) * 128 + c4);
        __half2* p = (__half2*)(As + r * SH_STRIDE + c4);
        p[0] = __floats2half2_rn(v.x, v.y);
        p[1] = __floats2half2_rn(v.z, v.w);
    }
    // B fill: W1 [k][n] fp32 -> Bs [n][k] fp16 (transpose)
    #pragma unroll
    for (int i = 0; i < 32; i++) {
        int f = tid + i * 256;             // 0..8191 (n, kpair)
        int nn = f & 127, kp = f >> 7;     // kp 0..63
        float w0 = W[(size_t)(2 * kp)     * 128 + nn];
        float w1 = W[(size_t)(2 * kp + 1) * 128 + nn];
        *(__half2*)(Bs + nn * SH_STRIDE + 2 * kp) = __floats2half2_rn(w0, w1);
    }
    __syncthreads();

    float acc[2][8][4];
    #pragma unroll
    for (int a = 0; a < 2; a++)
        #pragma unroll
        for (int j = 0; j < 8; j++)
            #pragma unroll
            for (int q = 0; q < 4; q++) acc[a][j][q] = 0.f;

    #pragma unroll
    for (int ks = 0; ks < 8; ks++) {       // K=16 per step
        int kb = ks * 16;
        uint32_t a[2][4];
        #pragma unroll
        for (int mf = 0; mf < 2; mf++) {
            int r = m0 + mf * 16 + gr;
            const __half* pr0 = As + (size_t)r * SH_STRIDE + kb + 2 * gc;
            const __half* pr1 = As + (size_t)(r + 8) * SH_STRIDE + kb + 2 * gc;
            a[mf][0] = *(const uint32_t*)(pr0);
            a[mf][1] = *(const uint32_t*)(pr1);
            a[mf][2] = *(const uint32_t*)(pr0 + 8);
            a[mf][3] = *(const uint32_t*)(pr1 + 8);
        }
        #pragma unroll
        for (int j = 0; j < 8; j++) {
            int nn = n0 + j * 8 + gr;
            const __half* pb = Bs + (size_t)nn * SH_STRIDE + kb + 2 * gc;
            uint32_t b0 = *(const uint32_t*)(pb);
            uint32_t b1 = *(const uint32_t*)(pb + 8);
            mma_f16(acc[0][j], a[0], b0, b1);
            mma_f16(acc[1][j], a[1], b0, b1);
        }
    }

    // epilogue: *dis, write hs1 fp16
    #pragma unroll
    for (int mf = 0; mf < 2; mf++) {
        int r0 = bm + m0 + mf * 16 + gr;
        int r1 = r0 + 8;
        float d0 = (r0 < m) ? g_dis[r0] : 0.f;
        float d1 = (r1 < m) ? g_dis[r1] : 0.f;
        #pragma unroll
        for (int j = 0; j < 8; j++) {
            int col = n0 + j * 8 + gc * 2;
            if (r0 < m)
                *(__half2*)(g_hs1 + (size_t)r0 * 128 + col) =
                    __floats2half2_rn(acc[mf][j][0] * d0, acc[mf][j][1] * d0);
            if (r1 < m)
                *(__half2*)(g_hs1 + (size_t)r1 * 128 + col) =
                    __floats2half2_rn(acc[mf][j][2] * d1, acc[mf][j][3] * d1);
        }
    }
}

// -------------------- GEMM 2 (fp16 mma m16n8k16): hs2 = (x2@W2)*dis --------
// CTA 128m x 64n. As copied raw from fp16 x2. 8 warps of 32m x 32n. 52 KB smem.
#define G2_SMEM ((128 * SH_STRIDE + 64 * SH_STRIDE) * 2)

__global__ void __launch_bounds__(256)
k_gemm2_mma(const float* __restrict__ W, int m) {
    extern __shared__ __half sh[];
    __half* As = sh;                       // [128][136]
    __half* Bs = sh + 128 * SH_STRIDE;     // [64][136]  n-major
    const int tid  = threadIdx.x;
    const int lane = tid & 31;
    const int wid  = tid >> 5;
    const int gr   = lane >> 2;
    const int gc   = lane & 3;
    const int bm   = blockIdx.x * 128;
    const int m0   = (wid & 3) * 32;
    const int n0   = (wid >> 2) * 32;

    // A fill: raw uint4 copy of fp16 x2 rows
    #pragma unroll
    for (int i = 0; i < 8; i++) {
        int f = tid + i * 256;             // 0..2047 uint4 (8 halves)
        int r = f >> 4, c8 = (f & 15) * 8;
        uint4 v = make_uint4(0u, 0u, 0u, 0u);
        if (bm + r < m) v = *(const uint4*)(g_x2 + (size_t)(bm + r) * 128 + c8);
        *(uint4*)(As + r * SH_STRIDE + c8) = v;
    }
    // B fill: W2 [k][n] fp32 -> Bs [n][k] fp16 (transpose)
    #pragma unroll
    for (int i = 0; i < 16; i++) {
        int f = tid + i * 256;             // 0..4095 (n, kpair)
        int nn = f & 63, kp = f >> 6;      // kp 0..63
        float w0 = W[(size_t)(2 * kp)     * 64 + nn];
        float w1 = W[(size_t)(2 * kp + 1) * 64 + nn];
        *(__half2*)(Bs + nn * SH_STRIDE + 2 * kp) = __floats2half2_rn(w0, w1);
    }
    __syncthreads();

    float acc[2][4][4];
    #pragma unroll
    for (int a = 0; a < 2; a++)
        #pragma unroll
        for (int j = 0; j < 4; j++)
            #pragma unroll
            for (int q = 0; q < 4; q++) acc[a][j][q] = 0.f;

    #pragma unroll
    for (int ks = 0; ks < 8; ks++) {
        int kb = ks * 16;
        uint32_t a[2][4];
        #pragma unroll
        for (int mf = 0; mf < 2; mf++) {
            int r = m0 + mf * 16 + gr;
            const __half* pr0 = As + (size_t)r * SH_STRIDE + kb + 2 * gc;
            const __half* pr1 = As + (size_t)(r + 8) * SH_STRIDE + kb + 2 * gc;
            a[mf][0] = *(const uint32_t*)(pr0);
            a[mf][1] = *(const uint32_t*)(pr1);
            a[mf][2] = *(const uint32_t*)(pr0 + 8);
            a[mf][3] = *(const uint32_t*)(pr1 + 8);
        }
        #pragma unroll
        for (int j = 0; j < 4; j++) {
            int nn = n0 + j * 8 + gr;
            const __half* pb = Bs + (size_t)nn * SH_STRIDE + kb + 2 * gc;
            uint32_t b0 = *(const uint32_t*)(pb);
            uint32_t b1 = *(const uint32_t*)(pb + 8);
            mma_f16(acc[0][j], a[0], b0, b1);
            mma_f16(acc[1][j], a[1], b0, b1);
        }
    }

    #pragma unroll
    for (int mf = 0; mf < 2; mf++) {
        int r0 = bm + m0 + mf * 16 + gr;
        int r1 = r0 + 8;
        float d0 = (r0 < m) ? g_dis[r0] : 0.f;
        float d1 = (r1 < m) ? g_dis[r1] : 0.f;
        #pragma unroll
        for (int j = 0; j < 4; j++) {
            int col = n0 + j * 8 + gc * 2;
            if (r0 < m)
                *(__half2*)(g_hs2 + (size_t)r0 * 64 + col) =
                    __floats2half2_rn(acc[mf][j][0] * d0, acc[mf][j][1] * d0);
            if (r1 < m)
                *(__half2*)(g_hs2 + (size_t)r1 * 64 + col) =
                    __floats2half2_rn(acc[mf][j][2] * d1, acc[mf][j][3] * d1);
        }
    }
}

// -------------------- Aggregation 1: x2 = relu(dis*(hs1[v]+sum)+b1) --------
// warp per node; fp16 rows (256B/warp), fp32 accumulation, 4-way MLP unroll.
__global__ void k_agg1(const float* __restrict__ b1, int n) {
    int v = (blockIdx.x * blockDim.x + threadIdx.x) >> 5;
    if (v >= n) return;
    int lane = threadIdx.x & 31;
    int c = lane * 4;
    int s0 = g_rowptr[v], s1 = g_rowptr[v + 1];

    const __half* base = g_hs1 + c;
    uint2 us = *(const uint2*)(base + (size_t)v * 128);        // self term
    float2 f01 = __half22float2(*(__half2*)&us.x);
    float2 f23 = __half22float2(*(__half2*)&us.y);
    float4 acc0 = make_float4(f01.x, f01.y, f23.x, f23.y);
    float4 acc1 = make_float4(0.f, 0.f, 0.f, 0.f);
    float4 acc2 = make_float4(0.f, 0.f, 0.f, 0.f);
    float4 acc3 = make_float4(0.f, 0.f, 0.f, 0.f);

    for (int j = s0; j < s1; j += 32) {
        int mm = s1 - j; if (mm > 32) mm = 32;
        int sv = (lane < mm) ? g_csr[j + lane] : 0;
        int t = 0;
        for (; t + 3 < mm; t += 4) {
            int i0 = __shfl_sync(0xffffffffu, sv, t);
            int i1 = __shfl_sync(0xffffffffu, sv, t + 1);
            int i2 = __shfl_sync(0xffffffffu, sv, t + 2);
            int i3 = __shfl_sync(0xffffffffu, sv, t + 3);
            uint2 u0 = *(const uint2*)(base + (size_t)i0 * 128);
            uint2 u1 = *(const uint2*)(base + (size_t)i1 * 128);
            uint2 u2 = *(const uint2*)(base + (size_t)i2 * 128);
            uint2 u3 = *(const uint2*)(base + (size_t)i3 * 128);
            float2 a, b;
            a = __half22float2(*(__half2*)&u0.x); b = __half22float2(*(__half2*)&u0.y);
            acc0.x += a.x; acc0.y += a.y; acc0.z += b.x; acc0.w += b.y;
            a = __half22float2(*(__half2*)&u1.x); b = __half22float2(*(__half2*)&u1.y);
            acc1.x += a.x; acc1.y += a.y; acc1.z += b.x; acc1.w += b.y;
            a = __half22float2(*(__half2*)&u2.x); b = __half22float2(*(__half2*)&u2.y);
            acc2.x += a.x; acc2.y += a.y; acc2.z += b.x; acc2.w += b.y;
            a = __half22float2(*(__half2*)&u3.x); b = __half22float2(*(__half2*)&u3.y);
            acc3.x += a.x; acc3.y += a.y; acc3.z += b.x; acc3.w += b.y;
        }
        for (; t < mm; ++t) {
            int i0 = __shfl_sync(0xffffffffu, sv, t);
            uint2 u0 = *(const uint2*)(base + (size_t)i0 * 128);
            float2 a = __half22float2(*(__half2*)&u0.x);
            float2 b = __half22float2(*(__half2*)&u0.y);
            acc0.x += a.x; acc0.y += a.y; acc0.z += b.x; acc0.w += b.y;
        }
    }
    float dv = g_dis[v];
    float4 bb = *(const float4*)(b1 + c);
    float ox = fmaxf(fmaf(dv, acc0.x + acc1.x + acc2.x + acc3.x, bb.x), 0.f);
    float oy = fmaxf(fmaf(dv, acc0.y + acc1.y + acc2.y + acc3.y, bb.y), 0.f);
    float oz = fmaxf(fmaf(dv, acc0.z + acc1.z + acc2.z + acc3.z, bb.z), 0.f);
    float ow = fmaxf(fmaf(dv, acc0.w + acc1.w + acc2.w + acc3.w, bb.w), 0.f);
    __half2 h01 = __floats2half2_rn(ox, oy);
    __half2 h23 = __floats2half2_rn(oz, ow);
    uint2 pk;
    pk.x = *(uint32_t*)&h01;
    pk.y = *(uint32_t*)&h23;
    *(uint2*)(g_x2 + (size_t)v * 128 + c) = pk;
}

// -------------------- Aggregation 2: out = dis*(hs2[v]+sum)+b2 -------------
__global__ void k_agg2(const float* __restrict__ b2, float* __restrict__ out, int n) {
    int v = (blockIdx.x * blockDim.x + threadIdx.x) >> 5;
    if (v >= n) return;
    int lane = threadIdx.x & 31;
    int c = lane * 2;
    int s0 = g_rowptr[v], s1 = g_rowptr[v + 1];

    const __half* base = g_hs2 + c;
    float2 acc0 = __half22float2(*(const __half2*)(base + (size_t)v * 64));
    float2 acc1 = make_float2(0.f, 0.f);
    float2 acc2 = make_float2(0.f, 0.f);
    float2 acc3 = make_float2(0.f, 0.f);

    for (int j = s0; j < s1; j += 32) {
        int mm = s1 - j; if (mm > 32) mm = 32;
        int sv = (lane < mm) ? g_csr[j + lane] : 0;
        int t = 0;
        for (; t + 3 < mm; t += 4) {
            int i0 = __shfl_sync(0xffffffffu, sv, t);
            int i1 = __shfl_sync(0xffffffffu, sv, t + 1);
            int i2 = __shfl_sync(0xffffffffu, sv, t + 2);
            int i3 = __shfl_sync(0xffffffffu, sv, t + 3);
            float2 h0 = __half22float2(*(const __half2*)(base + (size_t)i0 * 64));
            float2 h1 = __half22float2(*(const __half2*)(base + (size_t)i1 * 64));
            float2 h2 = __half22float2(*(const __half2*)(base + (size_t)i2 * 64));
            float2 h3 = __half22float2(*(const __half2*)(base + (size_t)i3 * 64));
            acc0.x += h0.x; acc0.y += h0.y;
            acc1.x += h1.x; acc1.y += h1.y;
            acc2.x += h2.x; acc2.y += h2.y;
            acc3.x += h3.x; acc3.y += h3.y;
        }
        for (; t < mm; ++t) {
            int i0 = __shfl_sync(0xffffffffu, sv, t);
            float2 h0 = __half22float2(*(const __half2*)(base + (size_t)i0 * 64));
            acc0.x += h0.x; acc0.y += h0.y;
        }
    }
    float dv = g_dis[v];
    float2 bb = *(const float2*)(b2 + c);
    float2 o;
    o.x = fmaf(dv, acc0.x + acc1.x + acc2.x + acc3.x, bb.x);
    o.y = fmaf(dv, acc0.y + acc1.y + acc2.y + acc3.y, bb.y);
    *(float2*)(out + (size_t)v * 64 + c) = o;
}

// -------------------- launch ------------------------------------------------
extern "C" void kernel_launch(void* const* d_in, const int* in_sizes, int n_in,
                              void* d_out, int out_size) {
    const float* x  = (const float*)d_in[0];
    const int*   ei = (const int*)d_in[1];
    const float* W1 = (const float*)d_in[2];
    const float* b1 = (const float*)d_in[3];
    const float* W2 = (const float*)d_in[4];
    const float* b2 = (const float*)d_in[5];
    float* out = (float*)d_out;

    const int n = in_sizes[0] / INC;   // 100000
    const int e = in_sizes[1] / 2;     // 1600000
    const int* src = ei;
    const int* dst = ei + e;

    const int nb_n = (n + 255) / 256;  // 391
    const int nb_e = (e + 255) / 256;

    cudaFuncSetAttribute(k_gemm1_mma,
                         cudaFuncAttributeMaxDynamicSharedMemorySize, G1_SMEM);
    cudaFuncSetAttribute(k_gemm2_mma,
                         cudaFuncAttributeMaxDynamicSharedMemorySize, G2_SMEM);

    // CSR build + normalization (memset node + 5 kernels)
    void* cnt_addr = nullptr;
    cudaGetSymbolAddress(&cnt_addr, g_cnt);
    cudaMemsetAsync(cnt_addr, 0, (size_t)n * sizeof(int));
    k_count<<<nb_e, 256>>>(dst, e);
    k_scan_blocks<<<nb_n, 256>>>(n);
    k_scan_partials<<<1, 512>>>(nb_n, n);
    k_add_offsets<<<nb_n, 256>>>(n);
    k_fill<<<nb_e, 256>>>(src, dst, e);

    // Layer 1
    k_gemm1_mma<<<(n + 127) / 128, 256, G1_SMEM>>>(x, W1, n);
    k_agg1<<<(n + 7) / 8, 256>>>(b1, n);

    // Layer 2
    k_gemm2_mma<<<(n + 127) / 128, 256, G2_SMEM>>>(W2, n);
    k_agg2<<<(n + 7) / 8, 256>>>(b2, out, n);
}